// round 1
// baseline (speedup 1.0000x reference)
#include <cuda_runtime.h>
#include <cuda_bf16.h>

#define FULLMASK 0xffffffffu

// ---------------------------------------------------------------------------
// Analytic reduction of the reference circuit:
//
// The reference measures Z on TENSOR AXIS 10 (axis = N-1-center), i.e. wire 10
// in its apply_1q convention. Wire 10 is the "neighbor" qubit of edge-loop
// iteration i=1 and is acted on ONLY by (a) its vertex-init rotations and
// (b) iteration 1 of the edge loop. All later unitaries (iterations 2..7,
// the update strong_block, the H on wire 8) act on disjoint qubits and
// commute with Z_10, so they drop out of <Z_10>.
//
// The pre-loop state is a pure product. Hence:
//   psi0       = U |vE0> |vN0> |0>|0>               (16-dim, iteration-0 gates)
//   chi_{en}[a]= psi0[e, n, a]                       (anc branch vectors)
//   phi_{en}   = U (|vE1> |vN1> |chi_{en}>)          (same U: shared params)
//   answer     = sum_{en} <phi_{en}| Z_Nb |phi_{en}>
//
// Bit layout of the 4-qubit index s: E=bit3, Nb=bit2, A1=bit1, A2=bit0.
// ---------------------------------------------------------------------------

struct Ang { float c, s; };

__device__ __forceinline__ Ang mkang(float t){
    Ang a; sincosf(0.5f * t, &a.s, &a.c); return a;
}

__device__ __forceinline__ float2 cmulf(float2 a, float2 b){
    return make_float2(a.x*b.x - a.y*b.y, a.x*b.y + a.y*b.x);
}

__device__ __forceinline__ float2 shf2(float2 v, int m){
    float2 r;
    r.x = __shfl_xor_sync(FULLMASK, v.x, m);
    r.y = __shfl_xor_sync(FULLMASK, v.y, m);
    return r;
}

struct Params {
    Ang i0, i1, i2, i3;   // inits[0..3]
    Ang s0[3][3];         // strong0_params[0][qi][k]
    Ang s1[3][3];         // strong1_params[0][qi][k]
};

// Rz(t) = diag(e^{-it/2}, e^{+it/2}) — diagonal, no shuffle.
__device__ __forceinline__ void g_rz(float2& a, int s, int p, Ang g){
    int b = (s >> p) & 1;
    a = cmulf(a, make_float2(g.c, b ? g.s : -g.s));
}
// Ry(t) = [[c,-s],[s,c]]
__device__ __forceinline__ void g_ry(float2& a, int s, int p, Ang g){
    float2 ap = shf2(a, 1 << p);
    int b = (s >> p) & 1;
    float f = b ? g.s : -g.s;
    a.x = g.c * a.x + f * ap.x;
    a.y = g.c * a.y + f * ap.y;
}
// Rx(t) = [[c,-is],[-is,c]]
__device__ __forceinline__ void g_rx(float2& a, int s, int p, Ang g){
    float2 ap = shf2(a, 1 << p);
    a = make_float2(g.c * a.x + g.s * ap.y,
                    g.c * a.y - g.s * ap.x);
}
// Controlled versions: control qubit pc (first index of the 4x4 in the ref),
// target qubit pt. All lanes run the shuffle; only control=1 lanes update.
__device__ __forceinline__ void g_crz(float2& a, int s, int pc, int pt, Ang g){
    if ((s >> pc) & 1) {
        int b = (s >> pt) & 1;
        a = cmulf(a, make_float2(g.c, b ? g.s : -g.s));
    }
}
__device__ __forceinline__ void g_cry(float2& a, int s, int pc, int pt, Ang g){
    float2 ap = shf2(a, 1 << pt);
    if ((s >> pc) & 1) {
        int b = (s >> pt) & 1;
        float f = b ? g.s : -g.s;
        a.x = g.c * a.x + f * ap.x;
        a.y = g.c * a.y + f * ap.y;
    }
}
__device__ __forceinline__ void g_crx(float2& a, int s, int pc, int pt, Ang g){
    float2 ap = shf2(a, 1 << pt);
    if ((s >> pc) & 1) {
        a = make_float2(g.c * a.x + g.s * ap.y,
                        g.c * a.y - g.s * ap.x);
    }
}
__device__ __forceinline__ void g_cnot(float2& a, int s, int pc, int pt){
    float2 ap = shf2(a, 1 << pt);
    if ((s >> pc) & 1) a = ap;
}

// One edge-loop iteration: identical gate sequence both iterations.
// Wires: E=3, Nb=2, A1=1, A2=0.
__device__ __forceinline__ void evolve(float2& a, int s, const Params& P){
    // controlled init rotations
    g_crx(a, s, 2, 1, P.i0);   // ctrl(Rx(inits0)): control=Nb, target=A1
    g_cry(a, s, 3, 1, P.i1);   // ctrl(Ry(inits1)): control=E,  target=A1
    g_crz(a, s, 2, 0, P.i2);   // ctrl(Rz(inits2)): control=Nb, target=A2
    g_cry(a, s, 3, 0, P.i3);   // ctrl(Ry(inits3)): control=E,  target=A2
    // strong_block(strong0, [E, Nb, A1]): per-qubit Rz,Ry,Rx then ring CNOTs
    g_rz(a,s,3,P.s0[0][0]); g_ry(a,s,3,P.s0[0][1]); g_rx(a,s,3,P.s0[0][2]);
    g_rz(a,s,2,P.s0[1][0]); g_ry(a,s,2,P.s0[1][1]); g_rx(a,s,2,P.s0[1][2]);
    g_rz(a,s,1,P.s0[2][0]); g_ry(a,s,1,P.s0[2][1]); g_rx(a,s,1,P.s0[2][2]);
    g_cnot(a,s,3,2); g_cnot(a,s,2,1); g_cnot(a,s,1,3);
    // strong_block(strong1, [A1, Nb, A2])
    g_rz(a,s,1,P.s1[0][0]); g_ry(a,s,1,P.s1[0][1]); g_rx(a,s,1,P.s1[0][2]);
    g_rz(a,s,2,P.s1[1][0]); g_ry(a,s,2,P.s1[1][1]); g_rx(a,s,2,P.s1[1][2]);
    g_rz(a,s,0,P.s1[2][0]); g_ry(a,s,0,P.s1[2][1]); g_rx(a,s,0,P.s1[2][2]);
    g_cnot(a,s,1,2); g_cnot(a,s,2,0); g_cnot(a,s,0,1);
}

__global__ void QMessagePassing_44272522887312_kernel(
    const float* __restrict__ inp,     // inputs_flat [34]
    const float* __restrict__ inits,   // [4]
    const float* __restrict__ sp0,     // strong0_params [9]
    const float* __restrict__ sp1,     // strong1_params [9]
    float* __restrict__ out)
{
    __shared__ float2 psi0[16];
    __shared__ float partial[2];

    const int tid = threadIdx.x;
    const int s = tid & 15;

    Params P;
    P.i0 = mkang(inits[0]); P.i1 = mkang(inits[1]);
    P.i2 = mkang(inits[2]); P.i3 = mkang(inits[3]);
#pragma unroll
    for (int q = 0; q < 3; q++)
#pragma unroll
        for (int k = 0; k < 3; k++) {
            P.s0[q][k] = mkang(sp0[q*3 + k]);
            P.s1[q][k] = mkang(sp1[q*3 + k]);
        }

    // Single-qubit product states: v = Rz(phi) Ry(theta) |0>
    auto mkvec = [](float th, float ph, float2* v){
        float ct, st, cp, sp;
        sincosf(0.5f * th, &st, &ct);
        sincosf(0.5f * ph, &sp, &cp);
        v[0] = make_float2(ct*cp, -ct*sp);
        v[1] = make_float2(st*cp,  st*sp);
    };
    // adj[i] = inp[2i, 2i+1]; vert[j] = inp[16 + 2j, 17 + 2j]
    float2 vE0[2], vN0[2], vE1[2], vN1[2];
    mkvec(inp[0],  inp[1],  vE0);   // edge 0 (wire 0)
    mkvec(inp[18], inp[19], vN0);   // vert[1] (wire 9  = neighbor of edge 0)
    mkvec(inp[2],  inp[3],  vE1);   // edge 1 (wire 1)
    mkvec(inp[20], inp[21], vN1);   // vert[2] (wire 10 = neighbor of edge 1, MEASURED)

    // ---- Phase A: psi0 = U |vE0,vN0,0,0> (all 16-lane groups compute it
    // redundantly; shuffles with xor-mask <= 8 never cross a 16-lane group)
    float2 amp = ((s & 3) == 0)
        ? cmulf(vE0[(s >> 3) & 1], vN0[(s >> 2) & 1])
        : make_float2(0.f, 0.f);
    evolve(amp, s, P);

    if (tid < 16) psi0[s] = amp;
    __syncthreads();

    // ---- Phase B: four branches (e,n) in parallel across 64 threads
    const int en = tid >> 4;               // 0..3
    const int e = (en >> 1) & 1, n = en & 1;
    float2 chi = psi0[e*8 + n*4 + (s & 3)];
    amp = cmulf(chi, cmulf(vE1[(s >> 3) & 1], vN1[(s >> 2) & 1]));
    evolve(amp, s, P);

    // <Z> on the neighbor qubit (bit 2)
    float val = amp.x*amp.x + amp.y*amp.y;
    if ((s >> 2) & 1) val = -val;

    // reduce 64 -> 1
#pragma unroll
    for (int off = 16; off > 0; off >>= 1)
        val += __shfl_xor_sync(FULLMASK, val, off);
    if ((tid & 31) == 0) partial[tid >> 5] = val;
    __syncthreads();
    if (tid == 0) out[0] = partial[0] + partial[1];
}

extern "C" void kernel_launch(void* const* d_in, const int* in_sizes, int n_in,
                              void* d_out, int out_size)
{
    const float* inputs_flat = (const float*)d_in[0];
    const float* inits       = (const float*)d_in[1];
    const float* strong0     = (const float*)d_in[2];
    const float* strong1     = (const float*)d_in[3];
    // d_in[4] (update_params) provably does not affect the measured value.
    QMessagePassing_44272522887312_kernel<<<1, 64>>>(
        inputs_flat, inits, strong0, strong1, (float*)d_out);
}

// round 2
// speedup vs baseline: 1.7036x; 1.7036x over previous
#include <cuda_runtime.h>
#include <cuda_bf16.h>

#define FULLMASK 0xffffffffu

// ---------------------------------------------------------------------------
// Analytic reduction (validated in R1, rel_err ~1e-5):
// The reference measures Z on tensor axis 10 = wire 10, touched only by its
// vertex init and edge-loop iteration i=1. Everything later commutes with
// Z_10 and drops out. With the product initial state:
//   psi0      = U |vE0>|vN0>|0>|0>        (16-dim, iteration-0 gates)
//   chi_en[a] = psi0[e,n,a]
//   phi_en    = U (|vE1>|vN1>|chi_en>)    (same U, shared params)
//   answer    = sum_en <phi_en| Z_Nb |phi_en>
// Bit layout of 4-qubit index s: E=bit3, Nb=bit2, A1=bit1, A2=bit0.
//
// R2: fully register-resident state (16 amps = 32 regs/thread), zero
// shuffles in the gate chain, CNOTs as register permutations (free),
// Rz*Ry*Rx fused into single 2x2 matrices, __sincosf fast transcendentals.
// ---------------------------------------------------------------------------

struct C2 { float x, y; };
__device__ __forceinline__ C2 cmul(C2 a, C2 b){
    return { a.x*b.x - a.y*b.y, a.x*b.y + a.y*b.x };
}
__device__ __forceinline__ C2 cmadd(C2 a, C2 b, C2 acc){ // acc + a*b
    return { fmaf(a.x, b.x, fmaf(-a.y, b.y, acc.x)),
             fmaf(a.x, b.y, fmaf( a.y, b.x, acc.y)) };
}

struct M2 { C2 m00, m01, m10, m11; };

__device__ __forceinline__ M2 mmul(const M2& A, const M2& B){
    M2 R;
    R.m00 = cmadd(A.m01, B.m10, cmul(A.m00, B.m00));
    R.m01 = cmadd(A.m01, B.m11, cmul(A.m00, B.m01));
    R.m10 = cmadd(A.m11, B.m10, cmul(A.m10, B.m00));
    R.m11 = cmadd(A.m11, B.m11, cmul(A.m10, B.m01));
    return R;
}

__device__ __forceinline__ M2 m_rx(float t){
    float c, s; __sincosf(0.5f*t, &s, &c);
    return { {c,0.f}, {0.f,-s}, {0.f,-s}, {c,0.f} };
}
__device__ __forceinline__ M2 m_ry(float t){
    float c, s; __sincosf(0.5f*t, &s, &c);
    return { {c,0.f}, {-s,0.f}, {s,0.f}, {c,0.f} };
}
__device__ __forceinline__ M2 m_rz(float t){
    float c, s; __sincosf(0.5f*t, &s, &c);
    return { {c,-s}, {0.f,0.f}, {0.f,0.f}, {c,s} };
}
// Fused Rx(t2)*Ry(t1)*Rz(t0)  (reference applies Rz first, then Ry, then Rx)
__device__ __forceinline__ M2 m_fused(float t0, float t1, float t2){
    return mmul(m_rx(t2), mmul(m_ry(t1), m_rz(t0)));
}

// 1q gate on qubit P over the 16-amp register array
template<int P>
__device__ __forceinline__ void apply1(C2* a, const M2& U){
#pragma unroll
    for (int s0 = 0; s0 < 16; s0++){
        if (s0 & (1 << P)) continue;
        const int s1 = s0 | (1 << P);
        C2 a0 = a[s0], a1 = a[s1];
        a[s0] = cmadd(U.m01, a1, cmul(U.m00, a0));
        a[s1] = cmadd(U.m11, a1, cmul(U.m10, a0));
    }
}
// controlled-U: control qubit PC (|1> subspace), target PT
template<int PC, int PT>
__device__ __forceinline__ void applyc(C2* a, const M2& U){
#pragma unroll
    for (int s0 = 0; s0 < 16; s0++){
        if (!(s0 & (1 << PC)) || (s0 & (1 << PT))) continue;
        const int s1 = s0 | (1 << PT);
        C2 a0 = a[s0], a1 = a[s1];
        a[s0] = cmadd(U.m01, a1, cmul(U.m00, a0));
        a[s1] = cmadd(U.m11, a1, cmul(U.m10, a0));
    }
}
// CNOT: pure register permutation -> MOVs, renamed away by ptxas
template<int PC, int PT>
__device__ __forceinline__ void cnotg(C2* a){
#pragma unroll
    for (int s0 = 0; s0 < 16; s0++){
        if (!(s0 & (1 << PC)) || (s0 & (1 << PT))) continue;
        const int s1 = s0 | (1 << PT);
        C2 t = a[s0]; a[s0] = a[s1]; a[s1] = t;
    }
}

struct Gates {
    M2 ci0, ci1, ci2, ci3;     // controlled init rotations
    M2 A0, A1, A2;             // fused strong0 per-qubit (wires 3,2,1)
    M2 B0, B1, B2;             // fused strong1 per-qubit (wires 1,2,0)
};

__device__ __forceinline__ void evolve(C2* a, const Gates& G){
    applyc<2,1>(a, G.ci0);     // ctrl(Rx(i0)): Nb -> A1
    applyc<3,1>(a, G.ci1);     // ctrl(Ry(i1)): E  -> A1
    applyc<2,0>(a, G.ci2);     // ctrl(Rz(i2)): Nb -> A2
    applyc<3,0>(a, G.ci3);     // ctrl(Ry(i3)): E  -> A2
    // strong_block(strong0, [E,Nb,A1])
    apply1<3>(a, G.A0);
    apply1<2>(a, G.A1);
    apply1<1>(a, G.A2);
    cnotg<3,2>(a); cnotg<2,1>(a); cnotg<1,3>(a);
    // strong_block(strong1, [A1,Nb,A2])
    apply1<1>(a, G.B0);
    apply1<2>(a, G.B1);
    apply1<0>(a, G.B2);
    cnotg<1,2>(a); cnotg<2,0>(a); cnotg<0,1>(a);
}

__global__ void QMessagePassing_44272522887312_kernel(
    const float* __restrict__ inp,     // inputs_flat [34]
    const float* __restrict__ inits,   // [4]
    const float* __restrict__ sp0,     // strong0_params [9]
    const float* __restrict__ sp1,     // strong1_params [9]
    float* __restrict__ out)
{
    const int tid = threadIdx.x;

    Gates G;
    G.ci0 = m_rx(__ldg(inits + 0));
    G.ci1 = m_ry(__ldg(inits + 1));
    G.ci2 = m_rz(__ldg(inits + 2));
    G.ci3 = m_ry(__ldg(inits + 3));
    G.A0 = m_fused(__ldg(sp0+0), __ldg(sp0+1), __ldg(sp0+2));
    G.A1 = m_fused(__ldg(sp0+3), __ldg(sp0+4), __ldg(sp0+5));
    G.A2 = m_fused(__ldg(sp0+6), __ldg(sp0+7), __ldg(sp0+8));
    G.B0 = m_fused(__ldg(sp1+0), __ldg(sp1+1), __ldg(sp1+2));
    G.B1 = m_fused(__ldg(sp1+3), __ldg(sp1+4), __ldg(sp1+5));
    G.B2 = m_fused(__ldg(sp1+6), __ldg(sp1+7), __ldg(sp1+8));

    // single-qubit product vectors: v = Rz(phi) Ry(theta) |0>
    auto mkvec = [](float th, float ph, C2* v){
        float ct, st, cp, sp;
        __sincosf(0.5f*th, &st, &ct);
        __sincosf(0.5f*ph, &sp, &cp);
        v[0] = { ct*cp, -ct*sp };
        v[1] = { st*cp,  st*sp };
    };
    C2 vE0[2], vN0[2], vE1[2], vN1[2];
    mkvec(__ldg(inp+0),  __ldg(inp+1),  vE0);   // edge 0  (wire 0)
    mkvec(__ldg(inp+18), __ldg(inp+19), vN0);   // vert[1] (wire 9)
    mkvec(__ldg(inp+2),  __ldg(inp+3),  vE1);   // edge 1  (wire 1)
    mkvec(__ldg(inp+20), __ldg(inp+21), vN1);   // vert[2] (wire 10, measured)

    // ---- Phase A: psi0 = U |vE0,vN0,0,0>  (redundant on all lanes)
    C2 amp[16];
#pragma unroll
    for (int s = 0; s < 16; s++){
        if ((s & 3) == 0)
            amp[s] = cmul(vE0[(s >> 3) & 1], vN0[(s >> 2) & 1]);
        else
            amp[s] = { 0.f, 0.f };
    }
    evolve(amp, G);

    // ---- Phase B: branch (e,n) = tid&3 (each branch replicated x8)
    const int en = tid & 3;                    // base offset into psi0 = en*4
    C2 chi[4];
#pragma unroll
    for (int a = 0; a < 4; a++){
        C2 v = amp[a];
        if (en == 1) v = amp[4  + a];
        if (en == 2) v = amp[8  + a];
        if (en == 3) v = amp[12 + a];
        chi[a] = v;
    }
    C2 b[16];
#pragma unroll
    for (int s = 0; s < 16; s++)
        b[s] = cmul(chi[s & 3], cmul(vE1[(s >> 3) & 1], vN1[(s >> 2) & 1]));
    evolve(b, G);

    // <Z> on Nb (bit 2)
    float val = 0.f;
#pragma unroll
    for (int s = 0; s < 16; s++){
        float p = b[s].x*b[s].x + b[s].y*b[s].y;
        val += ((s >> 2) & 1) ? -p : p;
    }

    // warp reduce (each branch counted 8x) -> *1/8 exact
#pragma unroll
    for (int off = 16; off > 0; off >>= 1)
        val += __shfl_xor_sync(FULLMASK, val, off);
    if (tid == 0) out[0] = val * 0.125f;
}

extern "C" void kernel_launch(void* const* d_in, const int* in_sizes, int n_in,
                              void* d_out, int out_size)
{
    const float* inputs_flat = (const float*)d_in[0];
    const float* inits       = (const float*)d_in[1];
    const float* strong0     = (const float*)d_in[2];
    const float* strong1     = (const float*)d_in[3];
    // d_in[4] (update_params) provably does not affect the measured value.
    QMessagePassing_44272522887312_kernel<<<1, 32>>>(
        inputs_flat, inits, strong0, strong1, (float*)d_out);
}

// round 4
// speedup vs baseline: 2.2933x; 1.3462x over previous
#include <cuda_runtime.h>
#include <cuda_bf16.h>

#define FULLMASK 0xffffffffu

// ---------------------------------------------------------------------------
// Analytic reduction (validated R1/R2, rel_err ~1e-5..2e-5):
// Measured observable is Z on wire 10, touched only by its vertex init and
// edge-loop iteration i=1; everything later commutes and drops out.
//   psi0      = U |vE0>|vN0>|0>|0>           (16-dim, iteration-0 gates)
//   chi_en[a] = psi0[en*4 + a]
//   phi_en    = U (|vE1>|vN1>|chi_en>)       (same U, shared params)
//   answer    = sum_en <phi_en| Z_Nb |phi_en>
//
// R3: by linearity  phi_en = sum_a chi_en[a] * W_a  with
//   W_a = U(|vE1>|vN1>|a>)  — independent of psi0!
// So 5 independent 16-dim evolutions run CONCURRENTLY on lanes 0..4
// (critical path = 1 evolve instead of 2), then a tiny cross-lane combine:
//   answer = sum_en sum_s (+-) | sum_a psi0[en*4+a] * W_a[s] |^2
// Bit layout of 4-qubit index s: E=bit3, Nb=bit2, A1=bit1, A2=bit0.
// ---------------------------------------------------------------------------

struct C2 { float x, y; };
__device__ __forceinline__ C2 cmul(C2 a, C2 b){
    return { a.x*b.x - a.y*b.y, a.x*b.y + a.y*b.x };
}
__device__ __forceinline__ C2 cmadd(C2 a, C2 b, C2 acc){ // acc + a*b
    return { fmaf(a.x, b.x, fmaf(-a.y, b.y, acc.x)),
             fmaf(a.x, b.y, fmaf( a.y, b.x, acc.y)) };
}

struct M2 { C2 m00, m01, m10, m11; };

__device__ __forceinline__ M2 mmul(const M2& A, const M2& B){
    M2 R;
    R.m00 = cmadd(A.m01, B.m10, cmul(A.m00, B.m00));
    R.m01 = cmadd(A.m01, B.m11, cmul(A.m00, B.m01));
    R.m10 = cmadd(A.m11, B.m10, cmul(A.m10, B.m00));
    R.m11 = cmadd(A.m11, B.m11, cmul(A.m10, B.m01));
    return R;
}

__device__ __forceinline__ M2 m_rx(float t){
    float c, s; __sincosf(0.5f*t, &s, &c);
    return { {c,0.f}, {0.f,-s}, {0.f,-s}, {c,0.f} };
}
__device__ __forceinline__ M2 m_ry(float t){
    float c, s; __sincosf(0.5f*t, &s, &c);
    return { {c,0.f}, {-s,0.f}, {s,0.f}, {c,0.f} };
}
__device__ __forceinline__ M2 m_rz(float t){
    float c, s; __sincosf(0.5f*t, &s, &c);
    return { {c,-s}, {0.f,0.f}, {0.f,0.f}, {c,s} };
}
// Fused Rx(t2)*Ry(t1)*Rz(t0)  (reference applies Rz, then Ry, then Rx)
__device__ __forceinline__ M2 m_fused(float t0, float t1, float t2){
    return mmul(m_rx(t2), mmul(m_ry(t1), m_rz(t0)));
}

template<int P>
__device__ __forceinline__ void apply1(C2* a, const M2& U){
#pragma unroll
    for (int s0 = 0; s0 < 16; s0++){
        if (s0 & (1 << P)) continue;
        const int s1 = s0 | (1 << P);
        C2 a0 = a[s0], a1 = a[s1];
        a[s0] = cmadd(U.m01, a1, cmul(U.m00, a0));
        a[s1] = cmadd(U.m11, a1, cmul(U.m10, a0));
    }
}
template<int PC, int PT>
__device__ __forceinline__ void applyc(C2* a, const M2& U){
#pragma unroll
    for (int s0 = 0; s0 < 16; s0++){
        if (!(s0 & (1 << PC)) || (s0 & (1 << PT))) continue;
        const int s1 = s0 | (1 << PT);
        C2 a0 = a[s0], a1 = a[s1];
        a[s0] = cmadd(U.m01, a1, cmul(U.m00, a0));
        a[s1] = cmadd(U.m11, a1, cmul(U.m10, a0));
    }
}
template<int PC, int PT>
__device__ __forceinline__ void cnotg(C2* a){
#pragma unroll
    for (int s0 = 0; s0 < 16; s0++){
        if (!(s0 & (1 << PC)) || (s0 & (1 << PT))) continue;
        const int s1 = s0 | (1 << PT);
        C2 t = a[s0]; a[s0] = a[s1]; a[s1] = t;
    }
}

struct Gates {
    M2 ci0, ci1, ci2, ci3;     // controlled init rotations
    M2 A0, A1, A2;             // fused strong0 (wires 3,2,1)
    M2 B0, B1, B2;             // fused strong1 (wires 1,2,0)
};

__device__ __forceinline__ void evolve(C2* a, const Gates& G){
    applyc<2,1>(a, G.ci0);     // ctrl(Rx): Nb -> A1
    applyc<3,1>(a, G.ci1);     // ctrl(Ry): E  -> A1
    applyc<2,0>(a, G.ci2);     // ctrl(Rz): Nb -> A2
    applyc<3,0>(a, G.ci3);     // ctrl(Ry): E  -> A2
    apply1<3>(a, G.A0);
    apply1<2>(a, G.A1);
    apply1<1>(a, G.A2);
    cnotg<3,2>(a); cnotg<2,1>(a); cnotg<1,3>(a);
    apply1<1>(a, G.B0);
    apply1<2>(a, G.B1);
    apply1<0>(a, G.B2);
    cnotg<1,2>(a); cnotg<2,0>(a); cnotg<0,1>(a);
}

__global__ void QMessagePassing_44272522887312_kernel(
    const float* __restrict__ inp,     // inputs_flat [34]
    const float* __restrict__ inits,   // [4]
    const float* __restrict__ sp0,     // strong0_params [9]
    const float* __restrict__ sp1,     // strong1_params [9]
    float* __restrict__ out)
{
    // shared: W[a][s] for a=0..3 at sh[a*16+s]; psi0[s] at sh[64+s]
    __shared__ C2 sh[80];

    const int tid = threadIdx.x;

    // ---- issue all parameter loads up front (independent -> MLP)
    const float4 ii  = *(const float4*)inits;
    const float4 e01 = *(const float4*)(inp);        // inp[0..3]
    const float2 n0a = *(const float2*)(inp + 18);   // vert[1]
    const float2 n1a = *(const float2*)(inp + 20);   // vert[2] (measured wire)
    const float4 p0a = *(const float4*)(sp0);
    const float4 p0b = *(const float4*)(sp0 + 4);
    const float  p0c = __ldg(sp0 + 8);
    const float4 p1a = *(const float4*)(sp1);
    const float4 p1b = *(const float4*)(sp1 + 4);
    const float  p1c = __ldg(sp1 + 8);

    Gates G;
    G.ci0 = m_rx(ii.x);
    G.ci1 = m_ry(ii.y);
    G.ci2 = m_rz(ii.z);
    G.ci3 = m_ry(ii.w);
    G.A0 = m_fused(p0a.x, p0a.y, p0a.z);
    G.A1 = m_fused(p0a.w, p0b.x, p0b.y);
    G.A2 = m_fused(p0b.z, p0b.w, p0c);
    G.B0 = m_fused(p1a.x, p1a.y, p1a.z);
    G.B1 = m_fused(p1a.w, p1b.x, p1b.y);
    G.B2 = m_fused(p1b.z, p1b.w, p1c);

    // single-qubit product vectors: v = Rz(phi) Ry(theta) |0>
    auto mkvec = [](float th, float ph, C2* v){
        float ct, st, cp, sp;
        __sincosf(0.5f*th, &st, &ct);
        __sincosf(0.5f*ph, &sp, &cp);
        v[0] = { ct*cp, -ct*sp };
        v[1] = { st*cp,  st*sp };
    };
    C2 vE0[2], vN0[2], vE1[2], vN1[2];
    mkvec(e01.x, e01.y, vE0);   // edge 0  (wire 0)
    mkvec(n0a.x, n0a.y, vN0);   // vert[1] (wire 9)
    mkvec(e01.z, e01.w, vE1);   // edge 1  (wire 1)
    mkvec(n1a.x, n1a.y, vN1);   // vert[2] (wire 10, measured)

    // ---- 5 concurrent evolutions:
    //   task 0..3: W_a = U(|vE1,vN1,a>)     (anc bits = a)
    //   task 4   : psi0 = U(|vE0,vN0,0>)
    const int task = (tid < 4) ? tid : 4;
    const int anc  = (task == 4) ? 0 : task;
    C2 st[16];
#pragma unroll
    for (int s = 0; s < 16; s++){
        C2 prod = (task == 4)
            ? cmul(vE0[(s >> 3) & 1], vN0[(s >> 2) & 1])
            : cmul(vE1[(s >> 3) & 1], vN1[(s >> 2) & 1]);
        st[s] = ((s & 3) == anc) ? prod : C2{0.f, 0.f};
    }
    evolve(st, G);

    if (tid < 5){
#pragma unroll
        for (int s = 0; s < 16; s++)
            sh[task*16 + s] = st[s];
    }
    __syncwarp();

    // ---- combine: 64 terms (en in 0..3, s in 0..15), 2 per lane
    float val = 0.f;
#pragma unroll
    for (int k = 0; k < 2; k++){
        const int T  = tid + 32*k;
        const int en = T >> 4;
        const int s  = T & 15;
        C2 amp = {0.f, 0.f};
#pragma unroll
        for (int a = 0; a < 4; a++)
            amp = cmadd(sh[64 + en*4 + a], sh[a*16 + s], amp);
        float p = amp.x*amp.x + amp.y*amp.y;
        val += ((s >> 2) & 1) ? -p : p;
    }

#pragma unroll
    for (int off = 16; off > 0; off >>= 1)
        val += __shfl_xor_sync(FULLMASK, val, off);
    if (tid == 0) out[0] = val;
}

extern "C" void kernel_launch(void* const* d_in, const int* in_sizes, int n_in,
                              void* d_out, int out_size)
{
    const float* inputs_flat = (const float*)d_in[0];
    const float* inits       = (const float*)d_in[1];
    const float* strong0     = (const float*)d_in[2];
    const float* strong1     = (const float*)d_in[3];
    // d_in[4] (update_params) provably does not affect the measured value.
    QMessagePassing_44272522887312_kernel<<<1, 32>>>(
        inputs_flat, inits, strong0, strong1, (float*)d_out);
}